// round 3
// baseline (speedup 1.0000x reference)
#include <cuda_runtime.h>
#include <cstdint>

#define S_    2048
#define NH_   16
#define DK_   64
#define BHN   64          // B*NH
#define MROWS 8192        // B*S
#define PRED_ELEMS 8388608     // 4*2048*1024
#define ATTN_ELEMS 268435456   // 4*16*2048*2048

// ----------------------------- scratch globals ------------------------------
__device__ float g_q [(size_t)BHN * S_ * DK_];   // [bh][s][d]
__device__ float g_k [(size_t)BHN * S_ * DK_];   // [bh][s][d]
__device__ float g_kT[(size_t)BHN * DK_ * S_];   // [bh][d][s]
__device__ float g_v [(size_t)BHN * S_ * DK_];   // [bh][s][d]
__device__ float g_ho[(size_t)MROWS * 1024];     // [b*s][h*64+d]
__device__ float g_m   [BHN * S_];
__device__ float g_linv[BHN * S_];
__device__ int   g_mkind;
__device__ float g_attn_fb[(size_t)ATTN_ELEMS];  // fallback if out lacks attn
__device__ float g_pred_fb[(size_t)PRED_ELEMS];  // fallback if out lacks pred

// ------------------------ FMA-only exp (no MUFU) ----------------------------
__device__ __forceinline__ float fexp(float x) {
    float t  = fmaxf(x * 1.4426950408889634f, -126.0f);
    float z  = __fadd_rn(t, 12582912.0f);      // round-to-int magic (1.5*2^23)
    float fi = __fadd_rn(z, -12582912.0f);
    float f  = t - fi;                          // [-0.5, 0.5]
    float y  = f * 0.6931471805599453f;
    float p  = 1.0f + y*(1.0f + y*(0.5f + y*(0.16666667f +
                 y*(0.041666667f + y*0.0083333333f))));
    int   n  = (__float_as_int(z) & 0x7FFFFF) - 0x400000;   // == round(t)
    float sc = __int_as_float((n + 127) << 23);             // 2^n, n>=-126
    return sc * p;
}

// ----------------- mask dtype detection (u8 bool / i32 / f32) ---------------
__global__ void detect_kernel(const unsigned int* __restrict__ m) {
    __shared__ int bad_int, bad_float, seen_f1;
    if (threadIdx.x == 0) { bad_int = 0; bad_float = 0; seen_f1 = 0; }
    __syncthreads();
    for (int i = threadIdx.x; i < 4096; i += 256) {
        unsigned w = m[i];
        if (w != 0u && w != 1u)          bad_int   = 1;
        if (w != 0u && w != 0x3F800000u) bad_float = 1;
        if (w == 0x3F800000u)            seen_f1   = 1;
    }
    __syncthreads();
    if (threadIdx.x == 0) {
        if (!bad_float && seen_f1) g_mkind = 2;      // float32
        else if (!bad_int)         g_mkind = 1;      // int32
        else                       g_mkind = 0;      // 1-byte bool
    }
}

// ------------- 128x128x8 fp32 GEMM: A[8192x1024] @ W[1024x1024] -------------
// mode 0->g_q  1->g_k  2->g_v  (scattered per-head layout), 3->Cext row-major
__global__ void __launch_bounds__(256) gemm_kernel(const float* __restrict__ A,
                                                   const float* __restrict__ W,
                                                   float* __restrict__ Cext,
                                                   int mode) {
    __shared__ float As[8][128];
    __shared__ float Bs[8][128];
    const float* Ap = (mode == 3) ? g_ho : A;
    int tid = threadIdx.x;
    int bx = blockIdx.x, by = blockIdx.y;
    int arow  = tid >> 1;
    int acol4 = (tid & 1) << 2;
    int brow  = tid >> 5;
    int bcol4 = (tid & 31) << 2;
    int tr = (tid >> 4) << 3;
    int tc = (tid & 15) << 3;
    const float* Abase = Ap + (size_t)(by * 128) * 1024;
    const float* Bbase = W + bx * 128;
    float acc[8][8];
#pragma unroll
    for (int i = 0; i < 8; i++)
#pragma unroll
        for (int j = 0; j < 8; j++) acc[i][j] = 0.f;

    for (int k0 = 0; k0 < 1024; k0 += 8) {
        float4 av = *(const float4*)&Abase[(size_t)arow * 1024 + k0 + acol4];
        float4 bv = *(const float4*)&Bbase[(size_t)(k0 + brow) * 1024 + bcol4];
        As[acol4 + 0][arow] = av.x;
        As[acol4 + 1][arow] = av.y;
        As[acol4 + 2][arow] = av.z;
        As[acol4 + 3][arow] = av.w;
        *(float4*)&Bs[brow][bcol4] = bv;
        __syncthreads();
#pragma unroll
        for (int kk = 0; kk < 8; kk++) {
            float a[8], bb[8];
            *(float4*)&a[0]  = *(const float4*)&As[kk][tr];
            *(float4*)&a[4]  = *(const float4*)&As[kk][tr + 4];
            *(float4*)&bb[0] = *(const float4*)&Bs[kk][tc];
            *(float4*)&bb[4] = *(const float4*)&Bs[kk][tc + 4];
#pragma unroll
            for (int i = 0; i < 8; i++)
#pragma unroll
                for (int j = 0; j < 8; j++) acc[i][j] += a[i] * bb[j];
        }
        __syncthreads();
    }

    float* Cq = (mode == 0) ? g_q : ((mode == 1) ? g_k : g_v);
#pragma unroll
    for (int i = 0; i < 8; i++) {
        int mrow = by * 128 + tr + i;
        int b = mrow >> 11, s = mrow & 2047;
#pragma unroll
        for (int j = 0; j < 8; j += 4) {
            int ncol = bx * 128 + tc + j;
            float4 v = make_float4(acc[i][j], acc[i][j+1], acc[i][j+2], acc[i][j+3]);
            if (mode == 3) {
                *(float4*)&Cext[(size_t)mrow * 1024 + ncol] = v;
            } else {
                int h = ncol >> 6, d = ncol & 63;
                *(float4*)&Cq[((size_t)(b * NH_ + h) * S_ + s) * DK_ + d] = v;
            }
        }
    }
}

// -------------------- K transpose: g_k[bh][s][d] -> g_kT[bh][d][s] ----------
__global__ void transpose_k_kernel() {
    __shared__ float t[32][33];
    int bh = blockIdx.z;
    int s0 = blockIdx.x * 32, d0 = blockIdx.y * 32;
    int tx = threadIdx.x, ty = threadIdx.y;
#pragma unroll
    for (int i = 0; i < 32; i += 8)
        t[ty + i][tx] = g_k[((size_t)bh * S_ + s0 + ty + i) * DK_ + d0 + tx];
    __syncthreads();
#pragma unroll
    for (int i = 0; i < 32; i += 8)
        g_kT[((size_t)bh * DK_ + d0 + ty + i) * S_ + s0 + tx] = t[tx][ty + i];
}

// ------ K1: scores = mask(scale(Q Kt)), write raw; online softmax stats -----
// block = (bh, 64-row q tile); 256 thr; 4x4 microtile over 64x64 score tiles
__global__ void __launch_bounds__(256) k1_scores(const void* __restrict__ mask,
                                                 float* __restrict__ attn) {
    __shared__ float sQ[64 * 65];
    __shared__ float sKt[64 * 68];
    int tid = threadIdx.x;
    int bid = blockIdx.x;
    int qt = bid & 31, bh = bid >> 5, b = bh >> 4;
    int q0 = qt << 6;
    int mkind = g_mkind;

#pragma unroll
    for (int j = 0; j < 4; j++) {
        int e = tid + j * 256;
        int r = e >> 4, c4 = (e & 15) << 2;
        float4 v = *(const float4*)&g_q[((size_t)(bh * S_ + q0 + r)) * DK_ + c4];
        sQ[r * 65 + c4]     = v.x;
        sQ[r * 65 + c4 + 1] = v.y;
        sQ[r * 65 + c4 + 2] = v.z;
        sQ[r * 65 + c4 + 3] = v.w;
    }
    __syncthreads();

    int rg = tid >> 4, cg = tid & 15;
    float mrun[4], srun[4];
#pragma unroll
    for (int i = 0; i < 4; i++) { mrun[i] = -3.0e38f; srun[i] = 0.f; }

    for (int k0 = 0; k0 < S_; k0 += 64) {
#pragma unroll
        for (int j = 0; j < 4; j++) {
            int e = tid + j * 256;
            int d = e >> 4, k4 = (e & 15) << 2;
            *(float4*)&sKt[d * 68 + k4] =
                *(const float4*)&g_kT[((size_t)(bh * DK_ + d)) * S_ + k0 + k4];
        }
        __syncthreads();

        float acc[4][4];
#pragma unroll
        for (int i = 0; i < 4; i++)
#pragma unroll
            for (int j = 0; j < 4; j++) acc[i][j] = 0.f;

#pragma unroll 4
        for (int d = 0; d < 64; d++) {
            float4 bv = *(const float4*)&sKt[d * 68 + (cg << 2)];
#pragma unroll
            for (int i = 0; i < 4; i++) {
                float a = sQ[(rg * 4 + i) * 65 + d];
                acc[i][0] += a * bv.x; acc[i][1] += a * bv.y;
                acc[i][2] += a * bv.z; acc[i][3] += a * bv.w;
            }
        }

#pragma unroll
        for (int i = 0; i < 4; i++) {
            int q = q0 + rg * 4 + i;
            float sv[4];
#pragma unroll
            for (int u = 0; u < 4; u++) sv[u] = acc[i][u] * 0.125f;
            size_t moff = ((size_t)b * S_ + q) * S_ + k0 + (cg << 2);
            if (mkind == 0) {
                uchar4 mv = *(const uchar4*)((const unsigned char*)mask + moff);
                if (mv.x) sv[0] = -1e9f;
                if (mv.y) sv[1] = -1e9f;
                if (mv.z) sv[2] = -1e9f;
                if (mv.w) sv[3] = -1e9f;
            } else if (mkind == 1) {
                int4 mv = *(const int4*)((const int*)mask + moff);
                if (mv.x) sv[0] = -1e9f;
                if (mv.y) sv[1] = -1e9f;
                if (mv.z) sv[2] = -1e9f;
                if (mv.w) sv[3] = -1e9f;
            } else {
                float4 mv = *(const float4*)((const float*)mask + moff);
                if (mv.x != 0.f) sv[0] = -1e9f;
                if (mv.y != 0.f) sv[1] = -1e9f;
                if (mv.z != 0.f) sv[2] = -1e9f;
                if (mv.w != 0.f) sv[3] = -1e9f;
            }
            *(float4*)&attn[((size_t)(bh * S_ + q)) * S_ + k0 + (cg << 2)] =
                make_float4(sv[0], sv[1], sv[2], sv[3]);
            float mt = fmaxf(fmaxf(sv[0], sv[1]), fmaxf(sv[2], sv[3]));
            float mn = fmaxf(mrun[i], mt);
            srun[i] = srun[i] * fexp(mrun[i] - mn)
                    + fexp(sv[0] - mn) + fexp(sv[1] - mn)
                    + fexp(sv[2] - mn) + fexp(sv[3] - mn);
            mrun[i] = mn;
        }
        __syncthreads();
    }

    // combine (m, s) across the 16 lanes of each row group
#pragma unroll
    for (int i = 0; i < 4; i++) {
        float m = mrun[i], s = srun[i];
#pragma unroll
        for (int o = 1; o < 16; o <<= 1) {
            float m2 = __shfl_xor_sync(0xffffffffu, m, o, 16);
            float s2 = __shfl_xor_sync(0xffffffffu, s, o, 16);
            float mn = fmaxf(m, m2);
            s = s * fexp(m - mn) + s2 * fexp(m2 - mn);
            m = mn;
        }
        if (cg == 0) {
            int gi = bh * S_ + q0 + rg * 4 + i;
            g_m[gi]    = m;
            g_linv[gi] = 1.0f / s;
        }
    }
}

// -------- K3: normalize attn in place + P@V -> g_ho[b*s][h*64+d] ------------
__global__ void __launch_bounds__(256) k3_pv(float* __restrict__ attn) {
    __shared__ float sP[64 * 68];
    __shared__ float sV[64 * 68];
    __shared__ float sM[64], sLi[64];
    int tid = threadIdx.x;
    int bid = blockIdx.x;
    int qt = bid & 31, bh = bid >> 5;
    int b = bh >> 4, h = bh & 15;
    int q0 = qt << 6;
    if (tid < 64) {
        int gi = bh * S_ + q0 + tid;
        sM[tid]  = g_m[gi];
        sLi[tid] = g_linv[gi];
    }
    __syncthreads();

    int rg = tid >> 4, cg = tid & 15;
    float acc[4][4];
#pragma unroll
    for (int i = 0; i < 4; i++)
#pragma unroll
        for (int j = 0; j < 4; j++) acc[i][j] = 0.f;

    for (int k0 = 0; k0 < S_; k0 += 64) {
#pragma unroll
        for (int j = 0; j < 4; j++) {
            int e = tid + j * 256;
            int r = e >> 4, k4 = (e & 15) << 2;
            size_t ai = ((size_t)(bh * S_ + q0 + r)) * S_ + k0 + k4;
            float4 v = *(const float4*)&attn[ai];
            float m = sM[r], li = sLi[r];
            v.x = fexp(v.x - m) * li;
            v.y = fexp(v.y - m) * li;
            v.z = fexp(v.z - m) * li;
            v.w = fexp(v.w - m) * li;
            *(float4*)&attn[ai] = v;
            *(float4*)&sP[r * 68 + k4] = v;
        }
#pragma unroll
        for (int j = 0; j < 4; j++) {
            int e = tid + j * 256;
            int kk = e >> 4, d4 = (e & 15) << 2;
            *(float4*)&sV[kk * 68 + d4] =
                *(const float4*)&g_v[((size_t)(bh * S_ + k0 + kk)) * DK_ + d4];
        }
        __syncthreads();

#pragma unroll 4
        for (int k = 0; k < 64; k++) {
            float4 bv = *(const float4*)&sV[k * 68 + (cg << 2)];
#pragma unroll
            for (int i = 0; i < 4; i++) {
                float a = sP[(rg * 4 + i) * 68 + k];
                acc[i][0] += a * bv.x; acc[i][1] += a * bv.y;
                acc[i][2] += a * bv.z; acc[i][3] += a * bv.w;
            }
        }
        __syncthreads();
    }

#pragma unroll
    for (int i = 0; i < 4; i++) {
        size_t row = (size_t)(b * S_ + q0 + rg * 4 + i) * 1024 + h * DK_ + (cg << 2);
        *(float4*)&g_ho[row] = make_float4(acc[i][0], acc[i][1], acc[i][2], acc[i][3]);
    }
}

// ----------------------------------------------------------------------------
extern "C" void kernel_launch(void* const* d_in, const int* in_sizes, int n_in,
                              void* d_out, int out_size) {
    const float* Q   = (const float*)d_in[0];
    const float* K   = (const float*)d_in[1];
    const float* V   = (const float*)d_in[2];
    const void*  Mk  = d_in[3];
    const float* W_Q = (const float*)d_in[4];
    const float* W_K = (const float*)d_in[5];
    const float* W_V = (const float*)d_in[6];
    const float* Wfc = (const float*)d_in[7];

    float* predp;
    float* attnp;
    if ((size_t)out_size >= (size_t)PRED_ELEMS + (size_t)ATTN_ELEMS) {
        predp = (float*)d_out;
        attnp = (float*)d_out + PRED_ELEMS;
    } else if (out_size == ATTN_ELEMS) {          // attn-only output
        void* p; cudaGetSymbolAddress(&p, g_pred_fb);
        predp = (float*)p;
        attnp = (float*)d_out;
    } else {                                      // pred-only output
        predp = (float*)d_out;
        void* p; cudaGetSymbolAddress(&p, g_attn_fb);
        attnp = (float*)p;
    }

    detect_kernel<<<1, 256>>>((const unsigned int*)Mk);

    dim3 gg(8, 64);
    gemm_kernel<<<gg, 256>>>(Q, W_Q, nullptr, 0);
    gemm_kernel<<<gg, 256>>>(K, W_K, nullptr, 1);
    gemm_kernel<<<gg, 256>>>(V, W_V, nullptr, 2);

    transpose_k_kernel<<<dim3(64, 2, 64), dim3(32, 8)>>>();

    k1_scores<<<2048, 256>>>(Mk, attnp);
    k3_pv<<<2048, 256>>>(attnp);

    gemm_kernel<<<gg, 256>>>(nullptr, Wfc, predp, 3);
}